// round 13
// baseline (speedup 1.0000x reference)
#include <cuda_runtime.h>
#include <cuda_fp16.h>
#include <math.h>
#include <stdint.h>

// ---------------------------------------------------------------------------
// GDTEncoder: graph attention + PPR diffusion + FFN
// N=50000, DEG=16 (dst-contiguous), D_IN=D_OUT=256, H=8, HD=32, DFF=1024
// fp16 mma.sync GEMMs: 128-thread CTAs, 64x64 warp tiles (3x better
// HMMA:LDSM ratio), 3-stage cp.async. ehet fused into G1 (2 heads/warp),
// warp-autonomous softmax+hop0, LDG.128 hop gathers, LN2 fused into final
// hop, fp16 residual. wconv merged into LN1 launch.
// ---------------------------------------------------------------------------

#define NN     50000
#define DEG    16
#define EDGES  (NN * DEG)
#define DIN    256
#define NH     8
#define HD     32
#define DOUT   256
#define DFF    1024
#define HOPS   5
#define ALPHA  0.15f
#define SLOPE  0.2f

// ---------------- scratch (static device globals; no allocation) -----------
__device__ __align__(256) float g_eh[(size_t)NN * NH];
__device__ __align__(256) float g_et[(size_t)NN * NH];
__device__ __align__(256) float g_a[(size_t)EDGES * NH];
__device__ __align__(256) float g_rst[(size_t)NN * DOUT];

__device__ __align__(256) __half g_h16[(size_t)NN * DIN];
__device__ __align__(256) __half g_f016[(size_t)NN * DOUT];
__device__ __align__(256) __half g_fa16[(size_t)NN * DOUT];
__device__ __align__(256) __half g_fb16[(size_t)NN * DOUT];
__device__ __align__(256) __half g_x16[(size_t)NN * DOUT];
__device__ __align__(256) __half g_t16[(size_t)NN * DFF];
__device__ __align__(256) __half g_went16[DOUT * DIN];
__device__ __align__(256) __half g_w116[DFF * DOUT];
__device__ __align__(256) __half g_w216[DOUT * DFF];

// ---------------- mma / cp.async helpers -----------------------------------
__device__ __forceinline__ void ldmat4(uint32_t& r0, uint32_t& r1,
                                       uint32_t& r2, uint32_t& r3,
                                       uint32_t addr) {
    asm volatile("ldmatrix.sync.aligned.m8n8.x4.shared.b16 {%0,%1,%2,%3}, [%4];"
                 : "=r"(r0), "=r"(r1), "=r"(r2), "=r"(r3) : "r"(addr));
}

__device__ __forceinline__ void mma_fp(float c[4],
                                       uint32_t a0, uint32_t a1, uint32_t a2, uint32_t a3,
                                       uint32_t b0, uint32_t b1) {
    asm volatile(
        "mma.sync.aligned.m16n8k16.row.col.f32.f16.f16.f32 "
        "{%0,%1,%2,%3}, {%4,%5,%6,%7}, {%8,%9}, {%0,%1,%2,%3};"
        : "+f"(c[0]), "+f"(c[1]), "+f"(c[2]), "+f"(c[3])
        : "r"(a0), "r"(a1), "r"(a2), "r"(a3), "r"(b0), "r"(b1));
}

__device__ __forceinline__ void cp16(uint32_t dst, const void* src, int sz) {
    asm volatile("cp.async.cg.shared.global [%0], [%1], 16, %2;\n"
                 :: "r"(dst), "l"(src), "r"(sz));
}
__device__ __forceinline__ void cp_commit() {
    asm volatile("cp.async.commit_group;\n" ::);
}
template <int N>
__device__ __forceinline__ void cp_waitg() {
    asm volatile("cp.async.wait_group %0;\n" :: "n"(N));
}

// ---------------- GEMM: C[M,N] = A[M,K] * B[N,K]^T, fp16 mma ---------------
// 128 threads, 4 warps, 64x64 warp tiles, BM=BN=128, BK=32, 3-stage ring.
// MODE 0: plain -> fp16 Ch + fused eh/et (2 heads per warp).
// MODE 1: relu(acc+bias) -> fp16 Ch.   MODE 2: acc+bias+resid -> fp32 C.
template <int MODE>
__global__ void __launch_bounds__(128, 2)
gemm_mma(const __half* __restrict__ A, const __half* __restrict__ B,
         const float* __restrict__ bias, const float* __restrict__ resid,
         float* __restrict__ C, __half* __restrict__ Ch,
         const float* __restrict__ attn_h, const float* __restrict__ attn_t,
         int M, int N, int K) {
    constexpr int LDS = 40;
    constexpr int MAT = 128 * LDS * 2;      // 10240 B
    constexpr int STAGE = 2 * MAT;          // 20480 B
    constexpr int STAGES = 3;

    extern __shared__ __align__(16) char dynsmem[];
    const uint32_t smem0 = (uint32_t)__cvta_generic_to_shared(dynsmem);

    const int tid  = threadIdx.x;
    const int m0   = blockIdx.y * 128;
    const int n0   = blockIdx.x * 128;
    const int wid  = tid >> 5;
    const int lane = tid & 31;
    const int wm   = (wid >> 1) * 64;
    const int wn   = (wid & 1) * 64;
    const int lg   = lane >> 3;
    const int lr   = lane & 7;

    // loader: thread t loads A row t and B row t (4 cp16 each)
    const int lrow = tid;
    const bool arow_ok = (m0 + lrow) < M;
    const int  a_sz = arow_ok ? 16 : 0;
    const __half* pA = A + (size_t)(m0 + lrow) * K;
    const __half* pB = B + (size_t)(n0 + lrow) * K;
    const uint32_t soff = (uint32_t)(lrow * 80);

    const int KT = K / 32;

    auto load_stage = [&](int kt, int s) {
        uint32_t sb = smem0 + s * STAGE + soff;
        int ko = kt * 32;
        #pragma unroll
        for (int c = 0; c < 4; c++) {
            cp16(sb + c * 16,       pA + ko + c * 8, a_sz);
            cp16(sb + MAT + c * 16, pB + ko + c * 8, 16);
        }
    };

    float acc[4][8][4];
    #pragma unroll
    for (int i = 0; i < 4; i++)
        #pragma unroll
        for (int j = 0; j < 8; j++)
            #pragma unroll
            for (int q = 0; q < 4; q++) acc[i][j][q] = 0.f;

    #pragma unroll
    for (int s = 0; s < STAGES - 1; s++) {
        load_stage(s, s);
        cp_commit();
    }

    int cslot = 0;
    int lslot = STAGES - 1;
    for (int kt = 0; kt < KT; kt++) {
        cp_waitg<STAGES - 2>();
        __syncthreads();

        int nk = kt + STAGES - 1;
        if (nk < KT) load_stage(nk, lslot);
        cp_commit();

        const uint32_t baseA = smem0 + cslot * STAGE;
        const uint32_t baseB = baseA + MAT;

        #pragma unroll
        for (int ks = 0; ks < 2; ks++) {
            const int kb = ks * 16;
            uint32_t bh[8][2];
            #pragma unroll
            for (int p = 0; p < 4; p++) {
                int row = wn + p * 16 + lr + (lg & 2) * 4;
                int kc  = kb + (lg & 1) * 8;
                uint32_t off = (uint32_t)(row * LDS + kc) * 2;
                ldmat4(bh[2*p][0], bh[2*p][1], bh[2*p+1][0], bh[2*p+1][1], baseB + off);
            }
            #pragma unroll
            for (int mi = 0; mi < 4; mi++) {
                int row = wm + mi * 16 + lr + (lg & 1) * 8;
                int kc  = kb + (lg & 2) * 4;
                uint32_t off = (uint32_t)(row * LDS + kc) * 2;
                uint32_t a0, a1, a2, a3;
                ldmat4(a0, a1, a2, a3, baseA + off);
                #pragma unroll
                for (int nj = 0; nj < 8; nj++)
                    mma_fp(acc[mi][nj], a0, a1, a2, a3, bh[nj][0], bh[nj][1]);
            }
        }
        cslot = (cslot + 1 == STAGES) ? 0 : cslot + 1;
        lslot = (lslot + 1 == STAGES) ? 0 : lslot + 1;
    }

    const int gr  = lane >> 2;
    const int gc2 = (lane & 3) * 2;

    // MODE 0: warp covers 2 heads (64 cols). attn vectors per nj/q.
    float avh[16], avt[16];
    int h0 = 0;
    if (MODE == 0) {
        h0 = (n0 + wn) >> 5;
        #pragma unroll
        for (int nj = 0; nj < 8; nj++)
            #pragma unroll
            for (int q = 0; q < 2; q++) {
                int hd = (nj >> 2);
                int col = (nj & 3) * 8 + gc2 + q;
                avh[nj * 2 + q] = attn_h[(h0 + hd) * HD + col];
                avt[nj * 2 + q] = attn_t[(h0 + hd) * HD + col];
            }
    }

    #pragma unroll
    for (int mi = 0; mi < 4; mi++) {
        #pragma unroll
        for (int half = 0; half < 2; half++) {
            int gm = m0 + wm + mi * 16 + gr + half * 8;
            if (gm >= M) continue;
            if (MODE == 0) {
                float seh[2] = {0.f, 0.f}, set[2] = {0.f, 0.f};
                #pragma unroll
                for (int nj = 0; nj < 8; nj++) {
                    float v0 = acc[mi][nj][half * 2 + 0];
                    float v1 = acc[mi][nj][half * 2 + 1];
                    int gn = n0 + wn + nj * 8 + gc2;
                    *(__half2*)(Ch + (size_t)gm * N + gn) =
                        __halves2half2(__float2half_rn(v0), __float2half_rn(v1));
                    int hd = nj >> 2;
                    seh[hd] += v0 * avh[nj * 2] + v1 * avh[nj * 2 + 1];
                    set[hd] += v0 * avt[nj * 2] + v1 * avt[nj * 2 + 1];
                }
                #pragma unroll
                for (int hd = 0; hd < 2; hd++) {
                    float a = seh[hd], b = set[hd];
                    a += __shfl_xor_sync(0xffffffffu, a, 1);
                    b += __shfl_xor_sync(0xffffffffu, b, 1);
                    a += __shfl_xor_sync(0xffffffffu, a, 2);
                    b += __shfl_xor_sync(0xffffffffu, b, 2);
                    if ((lane & 3) == 0) {
                        g_eh[(size_t)gm * NH + h0 + hd] = a;
                        g_et[(size_t)gm * NH + h0 + hd] = b;
                    }
                }
            } else {
                #pragma unroll
                for (int nj = 0; nj < 8; nj++) {
                    int gn = n0 + wn + nj * 8 + gc2;
                    float v0 = acc[mi][nj][half * 2 + 0];
                    float v1 = acc[mi][nj][half * 2 + 1];
                    if (MODE == 1) {
                        v0 = fmaxf(v0 + bias[gn], 0.f);
                        v1 = fmaxf(v1 + bias[gn + 1], 0.f);
                        *(__half2*)(Ch + (size_t)gm * N + gn) =
                            __halves2half2(__float2half_rn(v0), __float2half_rn(v1));
                    } else {
                        const float* rr = resid + (size_t)gm * N + gn;
                        v0 += bias[gn]     + rr[0];
                        v1 += bias[gn + 1] + rr[1];
                        *(float2*)(C + (size_t)gm * N + gn) = make_float2(v0, v1);
                    }
                }
            }
        }
    }
}

// ---------------- fused LN1 (fp16 out) + weight conversion -----------------
// blocks [0, 6250): LN1, 8 rows/block.  blocks [6250, 6826): weight fp32->fp16.
#define LN_BLOCKS   (NN / 8)                       // 6250
#define WC_TOTAL4   ((DOUT*DIN + DFF*DOUT + DOUT*DFF) / 4)   // 147456
#define WC_BLOCKS   ((WC_TOTAL4 + 255) / 256)      // 576

__global__ void prep_kernel(const float* __restrict__ in,
                            const float* __restrict__ g,
                            const float* __restrict__ b,
                            __half* __restrict__ out_16,
                            const float* __restrict__ went,
                            const float* __restrict__ w1,
                            const float* __restrict__ w2) {
    if (blockIdx.x >= LN_BLOCKS) {
        int idx = (blockIdx.x - LN_BLOCKS) * 256 + threadIdx.x;
        if (idx >= WC_TOTAL4) return;
        int i = idx * 4;
        const int N0 = DOUT * DIN;
        const int N1 = N0 + DFF * DOUT;
        const float* srcp;
        __half* dstp;
        int off;
        if (i < N0)      { srcp = went; dstp = g_went16; off = i; }
        else if (i < N1) { srcp = w1;   dstp = g_w116;   off = i - N0; }
        else             { srcp = w2;   dstp = g_w216;   off = i - N1; }
        float4 v = *(const float4*)(srcp + off);
        *(__half2*)(dstp + off)     = __halves2half2(__float2half_rn(v.x), __float2half_rn(v.y));
        *(__half2*)(dstp + off + 2) = __halves2half2(__float2half_rn(v.z), __float2half_rn(v.w));
        return;
    }

    int row  = blockIdx.x * 8 + (threadIdx.x >> 5);
    int lane = threadIdx.x & 31;
    const float* rp = in + (size_t)row * 256;
    float4 v0 = *(const float4*)(rp + lane * 8);
    float4 v1 = *(const float4*)(rp + lane * 8 + 4);
    float s  = v0.x + v0.y + v0.z + v0.w + v1.x + v1.y + v1.z + v1.w;
    float sq = v0.x*v0.x + v0.y*v0.y + v0.z*v0.z + v0.w*v0.w
             + v1.x*v1.x + v1.y*v1.y + v1.z*v1.z + v1.w*v1.w;
    #pragma unroll
    for (int o = 16; o > 0; o >>= 1) {
        s  += __shfl_xor_sync(0xffffffffu, s, o);
        sq += __shfl_xor_sync(0xffffffffu, sq, o);
    }
    float mu  = s * (1.0f / 256.0f);
    float var = sq * (1.0f / 256.0f) - mu * mu;
    float rs  = rsqrtf(var + 1e-5f);
    float4 g0 = *(const float4*)(g + lane * 8);
    float4 g1 = *(const float4*)(g + lane * 8 + 4);
    float4 b0 = *(const float4*)(b + lane * 8);
    float4 b1 = *(const float4*)(b + lane * 8 + 4);
    float y[8];
    y[0] = (v0.x - mu) * rs * g0.x + b0.x;
    y[1] = (v0.y - mu) * rs * g0.y + b0.y;
    y[2] = (v0.z - mu) * rs * g0.z + b0.z;
    y[3] = (v0.w - mu) * rs * g0.w + b0.w;
    y[4] = (v1.x - mu) * rs * g1.x + b1.x;
    y[5] = (v1.y - mu) * rs * g1.y + b1.y;
    y[6] = (v1.z - mu) * rs * g1.z + b1.z;
    y[7] = (v1.w - mu) * rs * g1.w + b1.w;
    size_t o8 = (size_t)row * 256 + lane * 8;
    __half2 oh[4];
    #pragma unroll
    for (int i = 0; i < 4; i++)
        oh[i] = __floats2half2_rn(y[i * 2], y[i * 2 + 1]);
    *(float4*)(out_16 + o8) = *(float4*)oh;
}

// ---------------- fused softmax + hop0, warp-autonomous (8 nodes/block) ----
__global__ void __launch_bounds__(256)
hop0v_kernel(const int* __restrict__ src) {
    int b = blockIdx.x;
    int t = threadIdx.x;
    int nn = t >> 5, tl = t & 31;
    int n = b * 8 + nn;

    __shared__ int   sraw[8][16];
    __shared__ float aw[8][128];

    if (tl < 16) sraw[nn][tl] = src[(size_t)n * 16 + tl];
    __syncwarp();

    int gg = tl >> 3, h = tl & 7;
    float etv = g_et[(size_t)n * NH + h];
    float e[4], ex[4];
    #pragma unroll
    for (int k = 0; k < 4; k++) {
        int j = gg * 4 + k;
        float v = g_eh[(size_t)sraw[nn][j] * NH + h] + etv;
        e[k] = (v > 0.f) ? v : SLOPE * v;
    }
    float m = fmaxf(fmaxf(e[0], e[1]), fmaxf(e[2], e[3]));
    m = fmaxf(m, __shfl_xor_sync(0xffffffffu, m, 8));
    m = fmaxf(m, __shfl_xor_sync(0xffffffffu, m, 16));
    float s = 0.f;
    #pragma unroll
    for (int k = 0; k < 4; k++) { ex[k] = __expf(e[k] - m); s += ex[k]; }
    s += __shfl_xor_sync(0xffffffffu, s, 8);
    s += __shfl_xor_sync(0xffffffffu, s, 16);
    float rinv = 1.0f / s;
    #pragma unroll
    for (int k = 0; k < 4; k++) {
        int j = gg * 4 + k;
        float a = ex[k] * rinv;
        aw[nn][j * 8 + h] = a;
        g_a[(size_t)n * 128 + j * 8 + h] = a;
    }
    __syncwarp();

    int hh = tl >> 2;
    float w[16];
    int   off[16];
    #pragma unroll
    for (int j = 0; j < 16; j++) {
        w[j]   = aw[nn][j * 8 + hh];
        off[j] = sraw[nn][j] * 32;
    }

    const float4* fin = (const float4*)g_f016;
    float acc[8];
    #pragma unroll
    for (int q = 0; q < 8; q++) acc[q] = 0.f;
    #pragma unroll
    for (int j = 0; j < 16; j++) {
        float4 v = fin[(size_t)off[j] + tl];
        const __half2* hp = (const __half2*)&v;
        #pragma unroll
        for (int q = 0; q < 4; q++) {
            float2 f = __half22float2(hp[q]);
            acc[q * 2]     += w[j] * f.x;
            acc[q * 2 + 1] += w[j] * f.y;
        }
    }
    float4 f0v = fin[(size_t)n * 32 + tl];
    const __half2* f0p = (const __half2*)&f0v;
    __half2 oh[4];
    #pragma unroll
    for (int q = 0; q < 4; q++) {
        float2 f = __half22float2(f0p[q]);
        float vx = (1.0f - ALPHA) * acc[q * 2]     + ALPHA * f.x;
        float vy = (1.0f - ALPHA) * acc[q * 2 + 1] + ALPHA * f.y;
        oh[q] = __floats2half2_rn(vx, vy);
    }
    ((float4*)g_fa16)[(size_t)n * 32 + tl] = *(float4*)oh;
}

// ---------------- vectorized hop smem staging ------------------------------
__device__ __forceinline__ void hop_stage(const int* __restrict__ src, int b,
                                          float (&aw)[8][128], int (&soff)[8][16]) {
    int t = threadIdx.x;
    float4 v = ((const float4*)g_a)[(size_t)b * 256 + t];
    *(float4*)&aw[t >> 5][(t & 31) * 4] = v;
    if (t < 128)
        soff[t >> 4][t & 15] = src[(size_t)b * 128 + t] * 32;
    __syncthreads();
}

// ---------------- hops 1..3, vectorized ------------------------------------
__global__ void __launch_bounds__(256)
hop16v_kernel(const int* __restrict__ src, int hop) {
    const float4* fin;
    float4* fout;
    if      (hop == 1) { fin = (const float4*)g_fa16; fout = (float4*)g_fb16; }
    else if (hop == 2) { fin = (const float4*)g_fb16; fout = (float4*)g_fa16; }
    else               { fin = (const float4*)g_fa16; fout = (float4*)g_fb16; }

    int b = blockIdx.x;
    int t = threadIdx.x;
    int nn = t >> 5, tl = t & 31;
    int n = b * 8 + nn;

    __shared__ float aw[8][128];
    __shared__ int   soff[8][16];
    hop_stage(src, b, aw, soff);

    int hh = tl >> 2;
    float w[16];
    int   off[16];
    #pragma unroll
    for (int j = 0; j < 16; j++) {
        w[j]   = aw[nn][j * 8 + hh];
        off[j] = soff[nn][j];
    }

    float acc[8];
    #pragma unroll
    for (int q = 0; q < 8; q++) acc[q] = 0.f;

    #pragma unroll
    for (int j = 0; j < 16; j++) {
        float4 v = fin[(size_t)off[j] + tl];
        const __half2* hp = (const __half2*)&v;
        #pragma unroll
        for (int q = 0; q < 4; q++) {
            float2 f = __half22float2(hp[q]);
            acc[q * 2]     += w[j] * f.x;
            acc[q * 2 + 1] += w[j] * f.y;
        }
    }

    float4 f0v = ((const float4*)g_f016)[(size_t)n * 32 + tl];
    const __half2* f0p = (const __half2*)&f0v;
    __half2 oh[4];
    #pragma unroll
    for (int q = 0; q < 4; q++) {
        float2 f = __half22float2(f0p[q]);
        float vx = (1.0f - ALPHA) * acc[q * 2]     + ALPHA * f.x;
        float vy = (1.0f - ALPHA) * acc[q * 2 + 1] + ALPHA * f.y;
        oh[q] = __floats2half2_rn(vx, vy);
    }
    fout[(size_t)n * 32 + tl] = *(float4*)oh;
}

// ---------------- final hop + fp16 residual + warp-local LN2 ---------------
__global__ void __launch_bounds__(256)
hoplastv_kernel(const int* __restrict__ src,
                const float* __restrict__ ln2_g,
                const float* __restrict__ ln2_b) {
    int b = blockIdx.x;
    int t = threadIdx.x;
    int nn = t >> 5, tl = t & 31;
    int n = b * 8 + nn;

    __shared__ float aw[8][128];
    __shared__ int   soff[8][16];
    hop_stage(src, b, aw, soff);

    int hh = tl >> 2;
    float w[16];
    int   off[16];
    #pragma unroll
    for (int j = 0; j < 16; j++) {
        w[j]   = aw[nn][j * 8 + hh];
        off[j] = soff[nn][j];
    }

    const float4* fin = (const float4*)g_fb16;
    float acc[8];
    #pragma unroll
    for (int q = 0; q < 8; q++) acc[q] = 0.f;

    #pragma unroll
    for (int j = 0; j < 16; j++) {
        float4 v = fin[(size_t)off[j] + tl];
        const __half2* hp = (const __half2*)&v;
        #pragma unroll
        for (int q = 0; q < 4; q++) {
            float2 f = __half22float2(hp[q]);
            acc[q * 2]     += w[j] * f.x;
            acc[q * 2 + 1] += w[j] * f.y;
        }
    }

    float4 f0v = ((const float4*)g_f016)[(size_t)n * 32 + tl];
    const __half2* f0p = (const __half2*)&f0v;
    float4 hv = ((const float4*)g_h16)[(size_t)n * 32 + tl];
    const __half2* hp2 = (const __half2*)&hv;
    float v[8];
    #pragma unroll
    for (int q = 0; q < 4; q++) {
        float2 f = __half22float2(f0p[q]);
        float2 hr = __half22float2(hp2[q]);
        v[q * 2]     = (1.0f - ALPHA) * acc[q * 2]     + ALPHA * f.x + hr.x;
        v[q * 2 + 1] = (1.0f - ALPHA) * acc[q * 2 + 1] + ALPHA * f.y + hr.y;
    }
    ((float4*)g_rst)[(size_t)n * 64 + tl * 2]     = make_float4(v[0], v[1], v[2], v[3]);
    ((float4*)g_rst)[(size_t)n * 64 + tl * 2 + 1] = make_float4(v[4], v[5], v[6], v[7]);

    float s = 0.f, sq = 0.f;
    #pragma unroll
    for (int q = 0; q < 8; q++) { s += v[q]; sq += v[q] * v[q]; }
    #pragma unroll
    for (int o = 16; o > 0; o >>= 1) {
        s  += __shfl_xor_sync(0xffffffffu, s, o);
        sq += __shfl_xor_sync(0xffffffffu, sq, o);
    }
    float mu  = s * (1.0f / 256.0f);
    float var = sq * (1.0f / 256.0f) - mu * mu;
    float rs  = rsqrtf(var + 1e-5f);

    float4 g0 = *(const float4*)(ln2_g + tl * 8);
    float4 g1 = *(const float4*)(ln2_g + tl * 8 + 4);
    float4 b0 = *(const float4*)(ln2_b + tl * 8);
    float4 b1 = *(const float4*)(ln2_b + tl * 8 + 4);
    float y[8];
    y[0] = (v[0] - mu) * rs * g0.x + b0.x;
    y[1] = (v[1] - mu) * rs * g0.y + b0.y;
    y[2] = (v[2] - mu) * rs * g0.z + b0.z;
    y[3] = (v[3] - mu) * rs * g0.w + b0.w;
    y[4] = (v[4] - mu) * rs * g1.x + b1.x;
    y[5] = (v[5] - mu) * rs * g1.y + b1.y;
    y[6] = (v[6] - mu) * rs * g1.z + b1.z;
    y[7] = (v[7] - mu) * rs * g1.w + b1.w;
    __half2 oh[4];
    #pragma unroll
    for (int q = 0; q < 4; q++)
        oh[q] = __floats2half2_rn(y[q * 2], y[q * 2 + 1]);
    ((float4*)g_x16)[(size_t)n * 32 + tl] = *(float4*)oh;
}

// ---------------------------------------------------------------------------
extern "C" void kernel_launch(void* const* d_in, const int* in_sizes, int n_in,
                              void* d_out, int out_size) {
    const float* ent_feat = (const float*)d_in[0];
    const float* W_ent    = (const float*)d_in[1];
    const float* attn_h   = (const float*)d_in[2];
    const float* attn_t   = (const float*)d_in[3];
    const float* ln1_g    = (const float*)d_in[4];
    const float* ln1_b    = (const float*)d_in[5];
    const float* ln2_g    = (const float*)d_in[6];
    const float* ln2_b    = (const float*)d_in[7];
    const float* W1       = (const float*)d_in[8];
    const float* b1       = (const float*)d_in[9];
    const float* W2       = (const float*)d_in[10];
    const float* b2       = (const float*)d_in[11];
    const int*   src      = (const int*)d_in[12];
    float*       out      = (float*)d_out;

    const int SMEM = 3 * 20480;
    cudaFuncSetAttribute(gemm_mma<0>, cudaFuncAttributeMaxDynamicSharedMemorySize, SMEM);
    cudaFuncSetAttribute(gemm_mma<1>, cudaFuncAttributeMaxDynamicSharedMemorySize, SMEM);
    cudaFuncSetAttribute(gemm_mma<2>, cudaFuncAttributeMaxDynamicSharedMemorySize, SMEM);

    float* p_rst;
    __half *p_h16, *p_f016, *p_x16, *p_t16, *p_went16, *p_w116, *p_w216;
    cudaGetSymbolAddress((void**)&p_rst,    g_rst);
    cudaGetSymbolAddress((void**)&p_h16,    g_h16);
    cudaGetSymbolAddress((void**)&p_f016,   g_f016);
    cudaGetSymbolAddress((void**)&p_x16,    g_x16);
    cudaGetSymbolAddress((void**)&p_t16,    g_t16);
    cudaGetSymbolAddress((void**)&p_went16, g_went16);
    cudaGetSymbolAddress((void**)&p_w116,   g_w116);
    cudaGetSymbolAddress((void**)&p_w216,   g_w216);

    // 1. fused LN1 + weight conversion
    prep_kernel<<<LN_BLOCKS + WC_BLOCKS, 256>>>(ent_feat, ln1_g, ln1_b, p_h16,
                                                W_ent, W1, W2);

    // 2. feat0 = h @ W_ent^T -> fp16, fused eh/et
    {
        dim3 grid(DOUT / 128, (NN + 127) / 128);
        gemm_mma<0><<<grid, 128, SMEM>>>(p_h16, p_went16, nullptr, nullptr,
                                         nullptr, p_f016, attn_h, attn_t,
                                         NN, DOUT, DIN);
    }

    // 3. fused softmax + hop0 (warp-autonomous)
    hop0v_kernel<<<NN / 8, 256>>>(src);

    // 4-6. hops 1..3 vectorized
    for (int hop = 1; hop < HOPS - 1; hop++)
        hop16v_kernel<<<NN / 8, 256>>>(src, hop);

    // 7. final hop + fp16 residual + warp-local LN2
    hoplastv_kernel<<<NN / 8, 256>>>(src, ln2_g, ln2_b);

    // 8. t = relu(x @ W1^T + b1) -> fp16
    {
        dim3 grid(DFF / 128, (NN + 127) / 128);
        gemm_mma<1><<<grid, 128, SMEM>>>(p_x16, p_w116, b1, nullptr,
                                         nullptr, p_t16, nullptr, nullptr,
                                         NN, DFF, DOUT);
    }

    // 9. out = t @ W2^T + b2 + rst  (fp32)
    {
        dim3 grid(DOUT / 128, (NN + 127) / 128);
        gemm_mma<2><<<grid, 128, SMEM>>>(p_t16, p_w216, b2, p_rst,
                                         out, nullptr, nullptr, nullptr,
                                         NN, DOUT, DFF);
    }
}

// round 14
// speedup vs baseline: 1.1224x; 1.1224x over previous
#include <cuda_runtime.h>
#include <cuda_fp16.h>
#include <math.h>
#include <stdint.h>

// ---------------------------------------------------------------------------
// GDTEncoder: graph attention + PPR diffusion + FFN
// N=50000, DEG=16 (dst-contiguous), D_IN=D_OUT=256, H=8, HD=32, DFF=1024
// fp16 mma.sync GEMMs: 256-thread CTAs, 64x32 warp tiles (R12 validated
// config), 3-stage cp.async, 2 CTA/SM. ehet fused into G1,
// warp-autonomous softmax+hop0, LDG.128 hop gathers, LN2 fused into final
// hop, fp16 residual. LN1 + weight conversion fused into one prep kernel.
// ---------------------------------------------------------------------------

#define NN     50000
#define DEG    16
#define EDGES  (NN * DEG)
#define DIN    256
#define NH     8
#define HD     32
#define DOUT   256
#define DFF    1024
#define HOPS   5
#define ALPHA  0.15f
#define SLOPE  0.2f

// ---------------- scratch (static device globals; no allocation) -----------
__device__ __align__(256) float g_eh[(size_t)NN * NH];
__device__ __align__(256) float g_et[(size_t)NN * NH];
__device__ __align__(256) float g_a[(size_t)EDGES * NH];
__device__ __align__(256) float g_rst[(size_t)NN * DOUT];

__device__ __align__(256) __half g_h16[(size_t)NN * DIN];
__device__ __align__(256) __half g_f016[(size_t)NN * DOUT];
__device__ __align__(256) __half g_fa16[(size_t)NN * DOUT];
__device__ __align__(256) __half g_fb16[(size_t)NN * DOUT];
__device__ __align__(256) __half g_x16[(size_t)NN * DOUT];
__device__ __align__(256) __half g_t16[(size_t)NN * DFF];
__device__ __align__(256) __half g_went16[DOUT * DIN];
__device__ __align__(256) __half g_w116[DFF * DOUT];
__device__ __align__(256) __half g_w216[DOUT * DFF];

// ---------------- mma / cp.async helpers -----------------------------------
__device__ __forceinline__ void ldmat4(uint32_t& r0, uint32_t& r1,
                                       uint32_t& r2, uint32_t& r3,
                                       uint32_t addr) {
    asm volatile("ldmatrix.sync.aligned.m8n8.x4.shared.b16 {%0,%1,%2,%3}, [%4];"
                 : "=r"(r0), "=r"(r1), "=r"(r2), "=r"(r3) : "r"(addr));
}

__device__ __forceinline__ void mma_fp(float c[4],
                                       uint32_t a0, uint32_t a1, uint32_t a2, uint32_t a3,
                                       uint32_t b0, uint32_t b1) {
    asm volatile(
        "mma.sync.aligned.m16n8k16.row.col.f32.f16.f16.f32 "
        "{%0,%1,%2,%3}, {%4,%5,%6,%7}, {%8,%9}, {%0,%1,%2,%3};"
        : "+f"(c[0]), "+f"(c[1]), "+f"(c[2]), "+f"(c[3])
        : "r"(a0), "r"(a1), "r"(a2), "r"(a3), "r"(b0), "r"(b1));
}

__device__ __forceinline__ void cp16(uint32_t dst, const void* src, int sz) {
    asm volatile("cp.async.cg.shared.global [%0], [%1], 16, %2;\n"
                 :: "r"(dst), "l"(src), "r"(sz));
}
__device__ __forceinline__ void cp_commit() {
    asm volatile("cp.async.commit_group;\n" ::);
}
template <int N>
__device__ __forceinline__ void cp_waitg() {
    asm volatile("cp.async.wait_group %0;\n" :: "n"(N));
}

// ---------------- GEMM: C[M,N] = A[M,K] * B[N,K]^T, fp16 mma ---------------
// R12-validated: 256 threads, 8 warps, 64x32 warp tiles, BM=BN=128, BK=32,
// 3-stage cp.async ring, 2 CTAs/SM.
// MODE 0: plain -> fp16 Ch + fused eh/et.  MODE 1: relu(acc+bias) -> fp16 Ch.
// MODE 2: acc+bias+resid -> fp32 C.
template <int MODE>
__global__ void __launch_bounds__(256, 2)
gemm_mma(const __half* __restrict__ A, const __half* __restrict__ B,
         const float* __restrict__ bias, const float* __restrict__ resid,
         float* __restrict__ C, __half* __restrict__ Ch,
         const float* __restrict__ attn_h, const float* __restrict__ attn_t,
         int M, int N, int K) {
    constexpr int LDS = 40;
    constexpr int MAT = 128 * LDS * 2;      // 10240 B
    constexpr int STAGE = 2 * MAT;          // 20480 B
    constexpr int STAGES = 3;

    extern __shared__ __align__(16) char dynsmem[];
    const uint32_t smem0 = (uint32_t)__cvta_generic_to_shared(dynsmem);

    const int tid  = threadIdx.x;
    const int m0   = blockIdx.y * 128;
    const int n0   = blockIdx.x * 128;
    const int wid  = tid >> 5;
    const int lane = tid & 31;
    const int wm   = (wid >> 2) * 64;
    const int wn   = (wid & 3) * 32;
    const int lg   = lane >> 3;
    const int lr   = lane & 7;

    const int lrow = tid >> 1;
    const int lc0  = (tid & 1) * 2;
    const bool arow_ok = (m0 + lrow) < M;
    const int  a_sz = arow_ok ? 16 : 0;
    const __half* pA = A + (size_t)(m0 + lrow) * K + lc0 * 8;
    const __half* pB = B + (size_t)(n0 + lrow) * K + lc0 * 8;
    const uint32_t soff = (uint32_t)(lrow * 80 + lc0 * 16);

    const int KT = K / 32;

    auto load_stage = [&](int kt, int s) {
        uint32_t sb = smem0 + s * STAGE + soff;
        int ko = kt * 32;
        cp16(sb,            pA + ko,     a_sz);
        cp16(sb + 16,       pA + ko + 8, a_sz);
        cp16(sb + MAT,      pB + ko,     16);
        cp16(sb + MAT + 16, pB + ko + 8, 16);
    };

    float acc[4][4][4];
    #pragma unroll
    for (int i = 0; i < 4; i++)
        #pragma unroll
        for (int j = 0; j < 4; j++)
            #pragma unroll
            for (int q = 0; q < 4; q++) acc[i][j][q] = 0.f;

    #pragma unroll
    for (int s = 0; s < STAGES - 1; s++) {
        load_stage(s, s);
        cp_commit();
    }

    int cslot = 0;
    int lslot = STAGES - 1;
    for (int kt = 0; kt < KT; kt++) {
        cp_waitg<STAGES - 2>();
        __syncthreads();

        int nk = kt + STAGES - 1;
        if (nk < KT) load_stage(nk, lslot);
        cp_commit();

        const uint32_t baseA = smem0 + cslot * STAGE;
        const uint32_t baseB = baseA + MAT;

        #pragma unroll
        for (int ks = 0; ks < 2; ks++) {
            const int kb = ks * 16;
            uint32_t bh[4][2];
            #pragma unroll
            for (int p = 0; p < 2; p++) {
                int row = wn + p * 16 + lr + (lg & 2) * 4;
                int kc  = kb + (lg & 1) * 8;
                uint32_t off = (uint32_t)(row * LDS + kc) * 2;
                ldmat4(bh[2*p][0], bh[2*p][1], bh[2*p+1][0], bh[2*p+1][1], baseB + off);
            }
            #pragma unroll
            for (int mi = 0; mi < 4; mi++) {
                int row = wm + mi * 16 + lr + (lg & 1) * 8;
                int kc  = kb + (lg & 2) * 4;
                uint32_t off = (uint32_t)(row * LDS + kc) * 2;
                uint32_t a0, a1, a2, a3;
                ldmat4(a0, a1, a2, a3, baseA + off);
                #pragma unroll
                for (int nj = 0; nj < 4; nj++)
                    mma_fp(acc[mi][nj], a0, a1, a2, a3, bh[nj][0], bh[nj][1]);
            }
        }
        cslot = (cslot + 1 == STAGES) ? 0 : cslot + 1;
        lslot = (lslot + 1 == STAGES) ? 0 : lslot + 1;
    }

    const int gr  = lane >> 2;
    const int gc2 = (lane & 3) * 2;

    float avh[8], avt[8];
    int hh = 0;
    if (MODE == 0) {
        hh = (n0 + wn) >> 5;
        #pragma unroll
        for (int nj = 0; nj < 4; nj++)
            #pragma unroll
            for (int q = 0; q < 2; q++) {
                int col = nj * 8 + gc2 + q;
                avh[nj * 2 + q] = attn_h[hh * HD + col];
                avt[nj * 2 + q] = attn_t[hh * HD + col];
            }
    }

    #pragma unroll
    for (int mi = 0; mi < 4; mi++) {
        #pragma unroll
        for (int half = 0; half < 2; half++) {
            int gm = m0 + wm + mi * 16 + gr + half * 8;
            if (gm >= M) continue;
            if (MODE == 0) {
                float seh = 0.f, set = 0.f;
                #pragma unroll
                for (int nj = 0; nj < 4; nj++) {
                    float v0 = acc[mi][nj][half * 2 + 0];
                    float v1 = acc[mi][nj][half * 2 + 1];
                    int gn = n0 + wn + nj * 8 + gc2;
                    *(__half2*)(Ch + (size_t)gm * N + gn) =
                        __halves2half2(__float2half_rn(v0), __float2half_rn(v1));
                    seh += v0 * avh[nj * 2] + v1 * avh[nj * 2 + 1];
                    set += v0 * avt[nj * 2] + v1 * avt[nj * 2 + 1];
                }
                seh += __shfl_xor_sync(0xffffffffu, seh, 1);
                set += __shfl_xor_sync(0xffffffffu, set, 1);
                seh += __shfl_xor_sync(0xffffffffu, seh, 2);
                set += __shfl_xor_sync(0xffffffffu, set, 2);
                if ((lane & 3) == 0) {
                    g_eh[(size_t)gm * NH + hh] = seh;
                    g_et[(size_t)gm * NH + hh] = set;
                }
            } else {
                #pragma unroll
                for (int nj = 0; nj < 4; nj++) {
                    int gn = n0 + wn + nj * 8 + gc2;
                    float v0 = acc[mi][nj][half * 2 + 0];
                    float v1 = acc[mi][nj][half * 2 + 1];
                    if (MODE == 1) {
                        v0 = fmaxf(v0 + bias[gn], 0.f);
                        v1 = fmaxf(v1 + bias[gn + 1], 0.f);
                        *(__half2*)(Ch + (size_t)gm * N + gn) =
                            __halves2half2(__float2half_rn(v0), __float2half_rn(v1));
                    } else {
                        const float* rr = resid + (size_t)gm * N + gn;
                        v0 += bias[gn]     + rr[0];
                        v1 += bias[gn + 1] + rr[1];
                        *(float2*)(C + (size_t)gm * N + gn) = make_float2(v0, v1);
                    }
                }
            }
        }
    }
}

// ---------------- fused LN1 (fp16 out) + weight conversion -----------------
#define LN_BLOCKS   (NN / 8)                                 // 6250
#define WC_TOTAL4   ((DOUT*DIN + DFF*DOUT + DOUT*DFF) / 4)   // 147456
#define WC_BLOCKS   ((WC_TOTAL4 + 255) / 256)                // 576

__global__ void prep_kernel(const float* __restrict__ in,
                            const float* __restrict__ g,
                            const float* __restrict__ b,
                            __half* __restrict__ out_16,
                            const float* __restrict__ went,
                            const float* __restrict__ w1,
                            const float* __restrict__ w2) {
    if (blockIdx.x >= LN_BLOCKS) {
        int idx = (blockIdx.x - LN_BLOCKS) * 256 + threadIdx.x;
        if (idx >= WC_TOTAL4) return;
        int i = idx * 4;
        const int N0 = DOUT * DIN;
        const int N1 = N0 + DFF * DOUT;
        const float* srcp;
        __half* dstp;
        int off;
        if (i < N0)      { srcp = went; dstp = g_went16; off = i; }
        else if (i < N1) { srcp = w1;   dstp = g_w116;   off = i - N0; }
        else             { srcp = w2;   dstp = g_w216;   off = i - N1; }
        float4 v = *(const float4*)(srcp + off);
        *(__half2*)(dstp + off)     = __halves2half2(__float2half_rn(v.x), __float2half_rn(v.y));
        *(__half2*)(dstp + off + 2) = __halves2half2(__float2half_rn(v.z), __float2half_rn(v.w));
        return;
    }

    int row  = blockIdx.x * 8 + (threadIdx.x >> 5);
    int lane = threadIdx.x & 31;
    const float* rp = in + (size_t)row * 256;
    float4 v0 = *(const float4*)(rp + lane * 8);
    float4 v1 = *(const float4*)(rp + lane * 8 + 4);
    float s  = v0.x + v0.y + v0.z + v0.w + v1.x + v1.y + v1.z + v1.w;
    float sq = v0.x*v0.x + v0.y*v0.y + v0.z*v0.z + v0.w*v0.w
             + v1.x*v1.x + v1.y*v1.y + v1.z*v1.z + v1.w*v1.w;
    #pragma unroll
    for (int o = 16; o > 0; o >>= 1) {
        s  += __shfl_xor_sync(0xffffffffu, s, o);
        sq += __shfl_xor_sync(0xffffffffu, sq, o);
    }
    float mu  = s * (1.0f / 256.0f);
    float var = sq * (1.0f / 256.0f) - mu * mu;
    float rs  = rsqrtf(var + 1e-5f);
    float4 g0 = *(const float4*)(g + lane * 8);
    float4 g1 = *(const float4*)(g + lane * 8 + 4);
    float4 b0 = *(const float4*)(b + lane * 8);
    float4 b1 = *(const float4*)(b + lane * 8 + 4);
    float y[8];
    y[0] = (v0.x - mu) * rs * g0.x + b0.x;
    y[1] = (v0.y - mu) * rs * g0.y + b0.y;
    y[2] = (v0.z - mu) * rs * g0.z + b0.z;
    y[3] = (v0.w - mu) * rs * g0.w + b0.w;
    y[4] = (v1.x - mu) * rs * g1.x + b1.x;
    y[5] = (v1.y - mu) * rs * g1.y + b1.y;
    y[6] = (v1.z - mu) * rs * g1.z + b1.z;
    y[7] = (v1.w - mu) * rs * g1.w + b1.w;
    size_t o8 = (size_t)row * 256 + lane * 8;
    __half2 oh[4];
    #pragma unroll
    for (int i = 0; i < 4; i++)
        oh[i] = __floats2half2_rn(y[i * 2], y[i * 2 + 1]);
    *(float4*)(out_16 + o8) = *(float4*)oh;
}

// ---------------- fused softmax + hop0, warp-autonomous (8 nodes/block) ----
__global__ void __launch_bounds__(256)
hop0v_kernel(const int* __restrict__ src) {
    int b = blockIdx.x;
    int t = threadIdx.x;
    int nn = t >> 5, tl = t & 31;
    int n = b * 8 + nn;

    __shared__ int   sraw[8][16];
    __shared__ float aw[8][128];

    if (tl < 16) sraw[nn][tl] = src[(size_t)n * 16 + tl];
    __syncwarp();

    int gg = tl >> 3, h = tl & 7;
    float etv = g_et[(size_t)n * NH + h];
    float e[4], ex[4];
    #pragma unroll
    for (int k = 0; k < 4; k++) {
        int j = gg * 4 + k;
        float v = g_eh[(size_t)sraw[nn][j] * NH + h] + etv;
        e[k] = (v > 0.f) ? v : SLOPE * v;
    }
    float m = fmaxf(fmaxf(e[0], e[1]), fmaxf(e[2], e[3]));
    m = fmaxf(m, __shfl_xor_sync(0xffffffffu, m, 8));
    m = fmaxf(m, __shfl_xor_sync(0xffffffffu, m, 16));
    float s = 0.f;
    #pragma unroll
    for (int k = 0; k < 4; k++) { ex[k] = __expf(e[k] - m); s += ex[k]; }
    s += __shfl_xor_sync(0xffffffffu, s, 8);
    s += __shfl_xor_sync(0xffffffffu, s, 16);
    float rinv = 1.0f / s;
    #pragma unroll
    for (int k = 0; k < 4; k++) {
        int j = gg * 4 + k;
        float a = ex[k] * rinv;
        aw[nn][j * 8 + h] = a;
        g_a[(size_t)n * 128 + j * 8 + h] = a;
    }
    __syncwarp();

    int hh = tl >> 2;
    float w[16];
    int   off[16];
    #pragma unroll
    for (int j = 0; j < 16; j++) {
        w[j]   = aw[nn][j * 8 + hh];
        off[j] = sraw[nn][j] * 32;
    }

    const float4* fin = (const float4*)g_f016;
    float acc[8];
    #pragma unroll
    for (int q = 0; q < 8; q++) acc[q] = 0.f;
    #pragma unroll
    for (int j = 0; j < 16; j++) {
        float4 v = fin[(size_t)off[j] + tl];
        const __half2* hp = (const __half2*)&v;
        #pragma unroll
        for (int q = 0; q < 4; q++) {
            float2 f = __half22float2(hp[q]);
            acc[q * 2]     += w[j] * f.x;
            acc[q * 2 + 1] += w[j] * f.y;
        }
    }
    float4 f0v = fin[(size_t)n * 32 + tl];
    const __half2* f0p = (const __half2*)&f0v;
    __half2 oh[4];
    #pragma unroll
    for (int q = 0; q < 4; q++) {
        float2 f = __half22float2(f0p[q]);
        float vx = (1.0f - ALPHA) * acc[q * 2]     + ALPHA * f.x;
        float vy = (1.0f - ALPHA) * acc[q * 2 + 1] + ALPHA * f.y;
        oh[q] = __floats2half2_rn(vx, vy);
    }
    ((float4*)g_fa16)[(size_t)n * 32 + tl] = *(float4*)oh;
}

// ---------------- vectorized hop smem staging ------------------------------
__device__ __forceinline__ void hop_stage(const int* __restrict__ src, int b,
                                          float (&aw)[8][128], int (&soff)[8][16]) {
    int t = threadIdx.x;
    float4 v = ((const float4*)g_a)[(size_t)b * 256 + t];
    *(float4*)&aw[t >> 5][(t & 31) * 4] = v;
    if (t < 128)
        soff[t >> 4][t & 15] = src[(size_t)b * 128 + t] * 32;
    __syncthreads();
}

// ---------------- hops 1..3, vectorized ------------------------------------
__global__ void __launch_bounds__(256)
hop16v_kernel(const int* __restrict__ src, int hop) {
    const float4* fin;
    float4* fout;
    if      (hop == 1) { fin = (const float4*)g_fa16; fout = (float4*)g_fb16; }
    else if (hop == 2) { fin = (const float4*)g_fb16; fout = (float4*)g_fa16; }
    else               { fin = (const float4*)g_fa16; fout = (float4*)g_fb16; }

    int b = blockIdx.x;
    int t = threadIdx.x;
    int nn = t >> 5, tl = t & 31;
    int n = b * 8 + nn;

    __shared__ float aw[8][128];
    __shared__ int   soff[8][16];
    hop_stage(src, b, aw, soff);

    int hh = tl >> 2;
    float w[16];
    int   off[16];
    #pragma unroll
    for (int j = 0; j < 16; j++) {
        w[j]   = aw[nn][j * 8 + hh];
        off[j] = soff[nn][j];
    }

    float acc[8];
    #pragma unroll
    for (int q = 0; q < 8; q++) acc[q] = 0.f;

    #pragma unroll
    for (int j = 0; j < 16; j++) {
        float4 v = fin[(size_t)off[j] + tl];
        const __half2* hp = (const __half2*)&v;
        #pragma unroll
        for (int q = 0; q < 4; q++) {
            float2 f = __half22float2(hp[q]);
            acc[q * 2]     += w[j] * f.x;
            acc[q * 2 + 1] += w[j] * f.y;
        }
    }

    float4 f0v = ((const float4*)g_f016)[(size_t)n * 32 + tl];
    const __half2* f0p = (const __half2*)&f0v;
    __half2 oh[4];
    #pragma unroll
    for (int q = 0; q < 4; q++) {
        float2 f = __half22float2(f0p[q]);
        float vx = (1.0f - ALPHA) * acc[q * 2]     + ALPHA * f.x;
        float vy = (1.0f - ALPHA) * acc[q * 2 + 1] + ALPHA * f.y;
        oh[q] = __floats2half2_rn(vx, vy);
    }
    fout[(size_t)n * 32 + tl] = *(float4*)oh;
}

// ---------------- final hop + fp16 residual + warp-local LN2 ---------------
__global__ void __launch_bounds__(256)
hoplastv_kernel(const int* __restrict__ src,
                const float* __restrict__ ln2_g,
                const float* __restrict__ ln2_b) {
    int b = blockIdx.x;
    int t = threadIdx.x;
    int nn = t >> 5, tl = t & 31;
    int n = b * 8 + nn;

    __shared__ float aw[8][128];
    __shared__ int   soff[8][16];
    hop_stage(src, b, aw, soff);

    int hh = tl >> 2;
    float w[16];
    int   off[16];
    #pragma unroll
    for (int j = 0; j < 16; j++) {
        w[j]   = aw[nn][j * 8 + hh];
        off[j] = soff[nn][j];
    }

    const float4* fin = (const float4*)g_fb16;
    float acc[8];
    #pragma unroll
    for (int q = 0; q < 8; q++) acc[q] = 0.f;

    #pragma unroll
    for (int j = 0; j < 16; j++) {
        float4 v = fin[(size_t)off[j] + tl];
        const __half2* hp = (const __half2*)&v;
        #pragma unroll
        for (int q = 0; q < 4; q++) {
            float2 f = __half22float2(hp[q]);
            acc[q * 2]     += w[j] * f.x;
            acc[q * 2 + 1] += w[j] * f.y;
        }
    }

    float4 f0v = ((const float4*)g_f016)[(size_t)n * 32 + tl];
    const __half2* f0p = (const __half2*)&f0v;
    float4 hv = ((const float4*)g_h16)[(size_t)n * 32 + tl];
    const __half2* hp2 = (const __half2*)&hv;
    float v[8];
    #pragma unroll
    for (int q = 0; q < 4; q++) {
        float2 f = __half22float2(f0p[q]);
        float2 hr = __half22float2(hp2[q]);
        v[q * 2]     = (1.0f - ALPHA) * acc[q * 2]     + ALPHA * f.x + hr.x;
        v[q * 2 + 1] = (1.0f - ALPHA) * acc[q * 2 + 1] + ALPHA * f.y + hr.y;
    }
    ((float4*)g_rst)[(size_t)n * 64 + tl * 2]     = make_float4(v[0], v[1], v[2], v[3]);
    ((float4*)g_rst)[(size_t)n * 64 + tl * 2 + 1] = make_float4(v[4], v[5], v[6], v[7]);

    float s = 0.f, sq = 0.f;
    #pragma unroll
    for (int q = 0; q < 8; q++) { s += v[q]; sq += v[q] * v[q]; }
    #pragma unroll
    for (int o = 16; o > 0; o >>= 1) {
        s  += __shfl_xor_sync(0xffffffffu, s, o);
        sq += __shfl_xor_sync(0xffffffffu, sq, o);
    }
    float mu  = s * (1.0f / 256.0f);
    float var = sq * (1.0f / 256.0f) - mu * mu;
    float rs  = rsqrtf(var + 1e-5f);

    float4 g0 = *(const float4*)(ln2_g + tl * 8);
    float4 g1 = *(const float4*)(ln2_g + tl * 8 + 4);
    float4 b0 = *(const float4*)(ln2_b + tl * 8);
    float4 b1 = *(const float4*)(ln2_b + tl * 8 + 4);
    float y[8];
    y[0] = (v[0] - mu) * rs * g0.x + b0.x;
    y[1] = (v[1] - mu) * rs * g0.y + b0.y;
    y[2] = (v[2] - mu) * rs * g0.z + b0.z;
    y[3] = (v[3] - mu) * rs * g0.w + b0.w;
    y[4] = (v[4] - mu) * rs * g1.x + b1.x;
    y[5] = (v[5] - mu) * rs * g1.y + b1.y;
    y[6] = (v[6] - mu) * rs * g1.z + b1.z;
    y[7] = (v[7] - mu) * rs * g1.w + b1.w;
    __half2 oh[4];
    #pragma unroll
    for (int q = 0; q < 4; q++)
        oh[q] = __floats2half2_rn(y[q * 2], y[q * 2 + 1]);
    ((float4*)g_x16)[(size_t)n * 32 + tl] = *(float4*)oh;
}

// ---------------------------------------------------------------------------
extern "C" void kernel_launch(void* const* d_in, const int* in_sizes, int n_in,
                              void* d_out, int out_size) {
    const float* ent_feat = (const float*)d_in[0];
    const float* W_ent    = (const float*)d_in[1];
    const float* attn_h   = (const float*)d_in[2];
    const float* attn_t   = (const float*)d_in[3];
    const float* ln1_g    = (const float*)d_in[4];
    const float* ln1_b    = (const float*)d_in[5];
    const float* ln2_g    = (const float*)d_in[6];
    const float* ln2_b    = (const float*)d_in[7];
    const float* W1       = (const float*)d_in[8];
    const float* b1       = (const float*)d_in[9];
    const float* W2       = (const float*)d_in[10];
    const float* b2       = (const float*)d_in[11];
    const int*   src      = (const int*)d_in[12];
    float*       out      = (float*)d_out;

    const int SMEM = 3 * 20480;
    cudaFuncSetAttribute(gemm_mma<0>, cudaFuncAttributeMaxDynamicSharedMemorySize, SMEM);
    cudaFuncSetAttribute(gemm_mma<1>, cudaFuncAttributeMaxDynamicSharedMemorySize, SMEM);
    cudaFuncSetAttribute(gemm_mma<2>, cudaFuncAttributeMaxDynamicSharedMemorySize, SMEM);

    float* p_rst;
    __half *p_h16, *p_f016, *p_x16, *p_t16, *p_went16, *p_w116, *p_w216;
    cudaGetSymbolAddress((void**)&p_rst,    g_rst);
    cudaGetSymbolAddress((void**)&p_h16,    g_h16);
    cudaGetSymbolAddress((void**)&p_f016,   g_f016);
    cudaGetSymbolAddress((void**)&p_x16,    g_x16);
    cudaGetSymbolAddress((void**)&p_t16,    g_t16);
    cudaGetSymbolAddress((void**)&p_went16, g_went16);
    cudaGetSymbolAddress((void**)&p_w116,   g_w116);
    cudaGetSymbolAddress((void**)&p_w216,   g_w216);

    // 1. fused LN1 + weight conversion
    prep_kernel<<<LN_BLOCKS + WC_BLOCKS, 256>>>(ent_feat, ln1_g, ln1_b, p_h16,
                                                W_ent, W1, W2);

    // 2. feat0 = h @ W_ent^T -> fp16, fused eh/et
    {
        dim3 grid(DOUT / 128, (NN + 127) / 128);
        gemm_mma<0><<<grid, 256, SMEM>>>(p_h16, p_went16, nullptr, nullptr,
                                         nullptr, p_f016, attn_h, attn_t,
                                         NN, DOUT, DIN);
    }

    // 3. fused softmax + hop0 (warp-autonomous)
    hop0v_kernel<<<NN / 8, 256>>>(src);

    // 4-6. hops 1..3 vectorized
    for (int hop = 1; hop < HOPS - 1; hop++)
        hop16v_kernel<<<NN / 8, 256>>>(src, hop);

    // 7. final hop + fp16 residual + warp-local LN2
    hoplastv_kernel<<<NN / 8, 256>>>(src, ln2_g, ln2_b);

    // 8. t = relu(x @ W1^T + b1) -> fp16
    {
        dim3 grid(DFF / 128, (NN + 127) / 128);
        gemm_mma<1><<<grid, 256, SMEM>>>(p_x16, p_w116, b1, nullptr,
                                         nullptr, p_t16, nullptr, nullptr,
                                         NN, DFF, DOUT);
    }

    // 9. out = t @ W2^T + b2 + rst  (fp32)
    {
        dim3 grid(DOUT / 128, (NN + 127) / 128);
        gemm_mma<2><<<grid, 256, SMEM>>>(p_t16, p_w216, b2, p_rst,
                                         out, nullptr, nullptr, nullptr,
                                         NN, DOUT, DFF);
    }
}

// round 15
// speedup vs baseline: 1.1657x; 1.0385x over previous
#include <cuda_runtime.h>
#include <cuda_fp16.h>
#include <math.h>
#include <stdint.h>

// ---------------------------------------------------------------------------
// GDTEncoder: graph attention + PPR diffusion + FFN
// N=50000, DEG=16 (dst-contiguous), D_IN=D_OUT=256, H=8, HD=32, DFF=1024
// fp16 mma.sync GEMMs: 256 threads, 64x32 warp tiles, BK=64 double-buffered
// cp.async (one sync per 64 k), 2 CTA/SM. ehet fused into G1,
// warp-autonomous softmax+hop0, LDG.128 hop gathers, LN2 fused into final
// hop, fp16 residual and fp16 rst. LN1 + weight conversion fused.
// ---------------------------------------------------------------------------

#define NN     50000
#define DEG    16
#define EDGES  (NN * DEG)
#define DIN    256
#define NH     8
#define HD     32
#define DOUT   256
#define DFF    1024
#define HOPS   5
#define ALPHA  0.15f
#define SLOPE  0.2f

// ---------------- scratch (static device globals; no allocation) -----------
__device__ __align__(256) float g_eh[(size_t)NN * NH];
__device__ __align__(256) float g_et[(size_t)NN * NH];
__device__ __align__(256) float g_a[(size_t)EDGES * NH];

__device__ __align__(256) __half g_h16[(size_t)NN * DIN];
__device__ __align__(256) __half g_f016[(size_t)NN * DOUT];
__device__ __align__(256) __half g_fa16[(size_t)NN * DOUT];
__device__ __align__(256) __half g_fb16[(size_t)NN * DOUT];
__device__ __align__(256) __half g_rst16[(size_t)NN * DOUT];  // rst fp16
__device__ __align__(256) __half g_x16[(size_t)NN * DOUT];
__device__ __align__(256) __half g_t16[(size_t)NN * DFF];
__device__ __align__(256) __half g_went16[DOUT * DIN];
__device__ __align__(256) __half g_w116[DFF * DOUT];
__device__ __align__(256) __half g_w216[DOUT * DFF];

// ---------------- mma / cp.async helpers -----------------------------------
__device__ __forceinline__ void ldmat4(uint32_t& r0, uint32_t& r1,
                                       uint32_t& r2, uint32_t& r3,
                                       uint32_t addr) {
    asm volatile("ldmatrix.sync.aligned.m8n8.x4.shared.b16 {%0,%1,%2,%3}, [%4];"
                 : "=r"(r0), "=r"(r1), "=r"(r2), "=r"(r3) : "r"(addr));
}

__device__ __forceinline__ void mma_fp(float c[4],
                                       uint32_t a0, uint32_t a1, uint32_t a2, uint32_t a3,
                                       uint32_t b0, uint32_t b1) {
    asm volatile(
        "mma.sync.aligned.m16n8k16.row.col.f32.f16.f16.f32 "
        "{%0,%1,%2,%3}, {%4,%5,%6,%7}, {%8,%9}, {%0,%1,%2,%3};"
        : "+f"(c[0]), "+f"(c[1]), "+f"(c[2]), "+f"(c[3])
        : "r"(a0), "r"(a1), "r"(a2), "r"(a3), "r"(b0), "r"(b1));
}

__device__ __forceinline__ void cp16(uint32_t dst, const void* src, int sz) {
    asm volatile("cp.async.cg.shared.global [%0], [%1], 16, %2;\n"
                 :: "r"(dst), "l"(src), "r"(sz));
}
__device__ __forceinline__ void cp_commit() {
    asm volatile("cp.async.commit_group;\n" ::);
}
template <int N>
__device__ __forceinline__ void cp_waitg() {
    asm volatile("cp.async.wait_group %0;\n" :: "n"(N));
}

// ---------------- GEMM: C[M,N] = A[M,K] * B[N,K]^T, fp16 mma ---------------
// 256 threads, 8 warps, 64x32 warp tiles, BM=BN=128, BK=64, double-buffered.
// Stage layout: [A(k0-31)][A(k32-63)][B(k0-31)][B(k32-63)], each 10240 B.
// MODE 0: plain -> fp16 Ch + fused eh/et.  MODE 1: relu(acc+bias) -> fp16 Ch.
// MODE 2: acc + bias + fp16 resid -> fp32 C.
// Requires K % 64 == 0 (K = 256 or 1024 here).
template <int MODE>
__global__ void __launch_bounds__(256, 2)
gemm_mma(const __half* __restrict__ A, const __half* __restrict__ B,
         const float* __restrict__ bias, const __half* __restrict__ resid,
         float* __restrict__ C, __half* __restrict__ Ch,
         const float* __restrict__ attn_h, const float* __restrict__ attn_t,
         int M, int N, int K) {
    constexpr int LDS = 40;
    constexpr int MAT = 128 * LDS * 2;      // 10240 B
    constexpr int STAGE = 4 * MAT;          // 40960 B (A0,A1,B0,B1)
    (void)STAGE;

    extern __shared__ __align__(16) char dynsmem[];
    const uint32_t smem0 = (uint32_t)__cvta_generic_to_shared(dynsmem);

    const int tid  = threadIdx.x;
    const int m0   = blockIdx.y * 128;
    const int n0   = blockIdx.x * 128;
    const int wid  = tid >> 5;
    const int lane = tid & 31;
    const int wm   = (wid >> 2) * 64;
    const int wn   = (wid & 3) * 32;
    const int lg   = lane >> 3;
    const int lr   = lane & 7;

    const int lrow = tid >> 1;
    const int lc0  = (tid & 1) * 2;
    const bool arow_ok = (m0 + lrow) < M;
    const int  a_sz = arow_ok ? 16 : 0;
    const __half* pA = A + (size_t)(m0 + lrow) * K + lc0 * 8;
    const __half* pB = B + (size_t)(n0 + lrow) * K + lc0 * 8;
    const uint32_t soff = (uint32_t)(lrow * 80 + lc0 * 16);

    const int KT = K / 64;

    auto load_stage = [&](int kt, int s) {
        uint32_t sb = smem0 + s * STAGE + soff;
        int ko = kt * 64;
        #pragma unroll
        for (int hf = 0; hf < 2; hf++) {
            cp16(sb + hf * MAT,                pA + ko + hf * 32,     a_sz);
            cp16(sb + hf * MAT + 16,           pA + ko + hf * 32 + 8, a_sz);
            cp16(sb + 2 * MAT + hf * MAT,      pB + ko + hf * 32,     16);
            cp16(sb + 2 * MAT + hf * MAT + 16, pB + ko + hf * 32 + 8, 16);
        }
    };

    float acc[4][4][4];
    #pragma unroll
    for (int i = 0; i < 4; i++)
        #pragma unroll
        for (int j = 0; j < 4; j++)
            #pragma unroll
            for (int q = 0; q < 4; q++) acc[i][j][q] = 0.f;

    load_stage(0, 0);
    cp_commit();

    for (int kt = 0; kt < KT; kt++) {
        cp_waitg<0>();              // stage kt landed
        __syncthreads();            // all warps done with the stage being refilled

        if (kt + 1 < KT) {
            load_stage(kt + 1, (kt + 1) & 1);
            cp_commit();
        }

        const uint32_t base = smem0 + (kt & 1) * STAGE;

        #pragma unroll
        for (int hf = 0; hf < 2; hf++) {
            const uint32_t baseA = base + hf * MAT;
            const uint32_t baseB = base + 2 * MAT + hf * MAT;
            #pragma unroll
            for (int ks = 0; ks < 2; ks++) {
                const int kb = ks * 16;
                uint32_t bh[4][2];
                #pragma unroll
                for (int p = 0; p < 2; p++) {
                    int row = wn + p * 16 + lr + (lg & 2) * 4;
                    int kc  = kb + (lg & 1) * 8;
                    uint32_t off = (uint32_t)(row * LDS + kc) * 2;
                    ldmat4(bh[2*p][0], bh[2*p][1], bh[2*p+1][0], bh[2*p+1][1], baseB + off);
                }
                #pragma unroll
                for (int mi = 0; mi < 4; mi++) {
                    int row = wm + mi * 16 + lr + (lg & 1) * 8;
                    int kc  = kb + (lg & 2) * 4;
                    uint32_t off = (uint32_t)(row * LDS + kc) * 2;
                    uint32_t a0, a1, a2, a3;
                    ldmat4(a0, a1, a2, a3, baseA + off);
                    #pragma unroll
                    for (int nj = 0; nj < 4; nj++)
                        mma_fp(acc[mi][nj], a0, a1, a2, a3, bh[nj][0], bh[nj][1]);
                }
            }
        }
    }

    const int gr  = lane >> 2;
    const int gc2 = (lane & 3) * 2;

    float avh[8], avt[8];
    int hh = 0;
    if (MODE == 0) {
        hh = (n0 + wn) >> 5;
        #pragma unroll
        for (int nj = 0; nj < 4; nj++)
            #pragma unroll
            for (int q = 0; q < 2; q++) {
                int col = nj * 8 + gc2 + q;
                avh[nj * 2 + q] = attn_h[hh * HD + col];
                avt[nj * 2 + q] = attn_t[hh * HD + col];
            }
    }

    #pragma unroll
    for (int mi = 0; mi < 4; mi++) {
        #pragma unroll
        for (int half = 0; half < 2; half++) {
            int gm = m0 + wm + mi * 16 + gr + half * 8;
            if (gm >= M) continue;
            if (MODE == 0) {
                float seh = 0.f, set = 0.f;
                #pragma unroll
                for (int nj = 0; nj < 4; nj++) {
                    float v0 = acc[mi][nj][half * 2 + 0];
                    float v1 = acc[mi][nj][half * 2 + 1];
                    int gn = n0 + wn + nj * 8 + gc2;
                    *(__half2*)(Ch + (size_t)gm * N + gn) =
                        __halves2half2(__float2half_rn(v0), __float2half_rn(v1));
                    seh += v0 * avh[nj * 2] + v1 * avh[nj * 2 + 1];
                    set += v0 * avt[nj * 2] + v1 * avt[nj * 2 + 1];
                }
                seh += __shfl_xor_sync(0xffffffffu, seh, 1);
                set += __shfl_xor_sync(0xffffffffu, set, 1);
                seh += __shfl_xor_sync(0xffffffffu, seh, 2);
                set += __shfl_xor_sync(0xffffffffu, set, 2);
                if ((lane & 3) == 0) {
                    g_eh[(size_t)gm * NH + hh] = seh;
                    g_et[(size_t)gm * NH + hh] = set;
                }
            } else {
                #pragma unroll
                for (int nj = 0; nj < 4; nj++) {
                    int gn = n0 + wn + nj * 8 + gc2;
                    float v0 = acc[mi][nj][half * 2 + 0];
                    float v1 = acc[mi][nj][half * 2 + 1];
                    if (MODE == 1) {
                        v0 = fmaxf(v0 + bias[gn], 0.f);
                        v1 = fmaxf(v1 + bias[gn + 1], 0.f);
                        *(__half2*)(Ch + (size_t)gm * N + gn) =
                            __halves2half2(__float2half_rn(v0), __float2half_rn(v1));
                    } else {
                        float2 hr = __half22float2(
                            *(const __half2*)(resid + (size_t)gm * N + gn));
                        v0 += bias[gn]     + hr.x;
                        v1 += bias[gn + 1] + hr.y;
                        *(float2*)(C + (size_t)gm * N + gn) = make_float2(v0, v1);
                    }
                }
            }
        }
    }
}

// ---------------- fused LN1 (fp16 out) + weight conversion -----------------
#define LN_BLOCKS   (NN / 8)                                 // 6250
#define WC_TOTAL4   ((DOUT*DIN + DFF*DOUT + DOUT*DFF) / 4)   // 147456
#define WC_BLOCKS   ((WC_TOTAL4 + 255) / 256)                // 576

__global__ void prep_kernel(const float* __restrict__ in,
                            const float* __restrict__ g,
                            const float* __restrict__ b,
                            __half* __restrict__ out_16,
                            const float* __restrict__ went,
                            const float* __restrict__ w1,
                            const float* __restrict__ w2) {
    if (blockIdx.x >= LN_BLOCKS) {
        int idx = (blockIdx.x - LN_BLOCKS) * 256 + threadIdx.x;
        if (idx >= WC_TOTAL4) return;
        int i = idx * 4;
        const int N0 = DOUT * DIN;
        const int N1 = N0 + DFF * DOUT;
        const float* srcp;
        __half* dstp;
        int off;
        if (i < N0)      { srcp = went; dstp = g_went16; off = i; }
        else if (i < N1) { srcp = w1;   dstp = g_w116;   off = i - N0; }
        else             { srcp = w2;   dstp = g_w216;   off = i - N1; }
        float4 v = *(const float4*)(srcp + off);
        *(__half2*)(dstp + off)     = __halves2half2(__float2half_rn(v.x), __float2half_rn(v.y));
        *(__half2*)(dstp + off + 2) = __halves2half2(__float2half_rn(v.z), __float2half_rn(v.w));
        return;
    }

    int row  = blockIdx.x * 8 + (threadIdx.x >> 5);
    int lane = threadIdx.x & 31;
    const float* rp = in + (size_t)row * 256;
    float4 v0 = *(const float4*)(rp + lane * 8);
    float4 v1 = *(const float4*)(rp + lane * 8 + 4);
    float s  = v0.x + v0.y + v0.z + v0.w + v1.x + v1.y + v1.z + v1.w;
    float sq = v0.x*v0.x + v0.y*v0.y + v0.z*v0.z + v0.w*v0.w
             + v1.x*v1.x + v1.y*v1.y + v1.z*v1.z + v1.w*v1.w;
    #pragma unroll
    for (int o = 16; o > 0; o >>= 1) {
        s  += __shfl_xor_sync(0xffffffffu, s, o);
        sq += __shfl_xor_sync(0xffffffffu, sq, o);
    }
    float mu  = s * (1.0f / 256.0f);
    float var = sq * (1.0f / 256.0f) - mu * mu;
    float rs  = rsqrtf(var + 1e-5f);
    float4 g0 = *(const float4*)(g + lane * 8);
    float4 g1 = *(const float4*)(g + lane * 8 + 4);
    float4 b0 = *(const float4*)(b + lane * 8);
    float4 b1 = *(const float4*)(b + lane * 8 + 4);
    float y[8];
    y[0] = (v0.x - mu) * rs * g0.x + b0.x;
    y[1] = (v0.y - mu) * rs * g0.y + b0.y;
    y[2] = (v0.z - mu) * rs * g0.z + b0.z;
    y[3] = (v0.w - mu) * rs * g0.w + b0.w;
    y[4] = (v1.x - mu) * rs * g1.x + b1.x;
    y[5] = (v1.y - mu) * rs * g1.y + b1.y;
    y[6] = (v1.z - mu) * rs * g1.z + b1.z;
    y[7] = (v1.w - mu) * rs * g1.w + b1.w;
    size_t o8 = (size_t)row * 256 + lane * 8;
    __half2 oh[4];
    #pragma unroll
    for (int i = 0; i < 4; i++)
        oh[i] = __floats2half2_rn(y[i * 2], y[i * 2 + 1]);
    *(float4*)(out_16 + o8) = *(float4*)oh;
}

// ---------------- fused softmax + hop0, warp-autonomous (8 nodes/block) ----
__global__ void __launch_bounds__(256)
hop0v_kernel(const int* __restrict__ src) {
    int b = blockIdx.x;
    int t = threadIdx.x;
    int nn = t >> 5, tl = t & 31;
    int n = b * 8 + nn;

    __shared__ int   sraw[8][16];
    __shared__ float aw[8][128];

    if (tl < 16) sraw[nn][tl] = src[(size_t)n * 16 + tl];
    __syncwarp();

    int gg = tl >> 3, h = tl & 7;
    float etv = g_et[(size_t)n * NH + h];
    float e[4], ex[4];
    #pragma unroll
    for (int k = 0; k < 4; k++) {
        int j = gg * 4 + k;
        float v = g_eh[(size_t)sraw[nn][j] * NH + h] + etv;
        e[k] = (v > 0.f) ? v : SLOPE * v;
    }
    float m = fmaxf(fmaxf(e[0], e[1]), fmaxf(e[2], e[3]));
    m = fmaxf(m, __shfl_xor_sync(0xffffffffu, m, 8));
    m = fmaxf(m, __shfl_xor_sync(0xffffffffu, m, 16));
    float s = 0.f;
    #pragma unroll
    for (int k = 0; k < 4; k++) { ex[k] = __expf(e[k] - m); s += ex[k]; }
    s += __shfl_xor_sync(0xffffffffu, s, 8);
    s += __shfl_xor_sync(0xffffffffu, s, 16);
    float rinv = 1.0f / s;
    #pragma unroll
    for (int k = 0; k < 4; k++) {
        int j = gg * 4 + k;
        float a = ex[k] * rinv;
        aw[nn][j * 8 + h] = a;
        g_a[(size_t)n * 128 + j * 8 + h] = a;
    }
    __syncwarp();

    int hh = tl >> 2;
    float w[16];
    int   off[16];
    #pragma unroll
    for (int j = 0; j < 16; j++) {
        w[j]   = aw[nn][j * 8 + hh];
        off[j] = sraw[nn][j] * 32;
    }

    const float4* fin = (const float4*)g_f016;
    float acc[8];
    #pragma unroll
    for (int q = 0; q < 8; q++) acc[q] = 0.f;
    #pragma unroll
    for (int j = 0; j < 16; j++) {
        float4 v = fin[(size_t)off[j] + tl];
        const __half2* hp = (const __half2*)&v;
        #pragma unroll
        for (int q = 0; q < 4; q++) {
            float2 f = __half22float2(hp[q]);
            acc[q * 2]     += w[j] * f.x;
            acc[q * 2 + 1] += w[j] * f.y;
        }
    }
    float4 f0v = fin[(size_t)n * 32 + tl];
    const __half2* f0p = (const __half2*)&f0v;
    __half2 oh[4];
    #pragma unroll
    for (int q = 0; q < 4; q++) {
        float2 f = __half22float2(f0p[q]);
        float vx = (1.0f - ALPHA) * acc[q * 2]     + ALPHA * f.x;
        float vy = (1.0f - ALPHA) * acc[q * 2 + 1] + ALPHA * f.y;
        oh[q] = __floats2half2_rn(vx, vy);
    }
    ((float4*)g_fa16)[(size_t)n * 32 + tl] = *(float4*)oh;
}

// ---------------- vectorized hop smem staging ------------------------------
__device__ __forceinline__ void hop_stage(const int* __restrict__ src, int b,
                                          float (&aw)[8][128], int (&soff)[8][16]) {
    int t = threadIdx.x;
    float4 v = ((const float4*)g_a)[(size_t)b * 256 + t];
    *(float4*)&aw[t >> 5][(t & 31) * 4] = v;
    if (t < 128)
        soff[t >> 4][t & 15] = src[(size_t)b * 128 + t] * 32;
    __syncthreads();
}

// ---------------- hops 1..3, vectorized ------------------------------------
__global__ void __launch_bounds__(256)
hop16v_kernel(const int* __restrict__ src, int hop) {
    const float4* fin;
    float4* fout;
    if      (hop == 1) { fin = (const float4*)g_fa16; fout = (float4*)g_fb16; }
    else if (hop == 2) { fin = (const float4*)g_fb16; fout = (float4*)g_fa16; }
    else               { fin = (const float4*)g_fa16; fout = (float4*)g_fb16; }

    int b = blockIdx.x;
    int t = threadIdx.x;
    int nn = t >> 5, tl = t & 31;
    int n = b * 8 + nn;

    __shared__ float aw[8][128];
    __shared__ int   soff[8][16];
    hop_stage(src, b, aw, soff);

    int hh = tl >> 2;
    float w[16];
    int   off[16];
    #pragma unroll
    for (int j = 0; j < 16; j++) {
        w[j]   = aw[nn][j * 8 + hh];
        off[j] = soff[nn][j];
    }

    float acc[8];
    #pragma unroll
    for (int q = 0; q < 8; q++) acc[q] = 0.f;

    #pragma unroll
    for (int j = 0; j < 16; j++) {
        float4 v = fin[(size_t)off[j] + tl];
        const __half2* hp = (const __half2*)&v;
        #pragma unroll
        for (int q = 0; q < 4; q++) {
            float2 f = __half22float2(hp[q]);
            acc[q * 2]     += w[j] * f.x;
            acc[q * 2 + 1] += w[j] * f.y;
        }
    }

    float4 f0v = ((const float4*)g_f016)[(size_t)n * 32 + tl];
    const __half2* f0p = (const __half2*)&f0v;
    __half2 oh[4];
    #pragma unroll
    for (int q = 0; q < 4; q++) {
        float2 f = __half22float2(f0p[q]);
        float vx = (1.0f - ALPHA) * acc[q * 2]     + ALPHA * f.x;
        float vy = (1.0f - ALPHA) * acc[q * 2 + 1] + ALPHA * f.y;
        oh[q] = __floats2half2_rn(vx, vy);
    }
    fout[(size_t)n * 32 + tl] = *(float4*)oh;
}

// ---------------- final hop + fp16 residual + warp-local LN2 ---------------
// writes rst as fp16 (g_rst16) and x = LN2(rst) as fp16 (g_x16)
__global__ void __launch_bounds__(256)
hoplastv_kernel(const int* __restrict__ src,
                const float* __restrict__ ln2_g,
                const float* __restrict__ ln2_b) {
    int b = blockIdx.x;
    int t = threadIdx.x;
    int nn = t >> 5, tl = t & 31;
    int n = b * 8 + nn;

    __shared__ float aw[8][128];
    __shared__ int   soff[8][16];
    hop_stage(src, b, aw, soff);

    int hh = tl >> 2;
    float w[16];
    int   off[16];
    #pragma unroll
    for (int j = 0; j < 16; j++) {
        w[j]   = aw[nn][j * 8 + hh];
        off[j] = soff[nn][j];
    }

    const float4* fin = (const float4*)g_fb16;
    float acc[8];
    #pragma unroll
    for (int q = 0; q < 8; q++) acc[q] = 0.f;

    #pragma unroll
    for (int j = 0; j < 16; j++) {
        float4 v = fin[(size_t)off[j] + tl];
        const __half2* hp = (const __half2*)&v;
        #pragma unroll
        for (int q = 0; q < 4; q++) {
            float2 f = __half22float2(hp[q]);
            acc[q * 2]     += w[j] * f.x;
            acc[q * 2 + 1] += w[j] * f.y;
        }
    }

    float4 f0v = ((const float4*)g_f016)[(size_t)n * 32 + tl];
    const __half2* f0p = (const __half2*)&f0v;
    float4 hv = ((const float4*)g_h16)[(size_t)n * 32 + tl];
    const __half2* hp2 = (const __half2*)&hv;
    float v[8];
    #pragma unroll
    for (int q = 0; q < 4; q++) {
        float2 f = __half22float2(f0p[q]);
        float2 hr = __half22float2(hp2[q]);
        v[q * 2]     = (1.0f - ALPHA) * acc[q * 2]     + ALPHA * f.x + hr.x;
        v[q * 2 + 1] = (1.0f - ALPHA) * acc[q * 2 + 1] + ALPHA * f.y + hr.y;
    }
    __half2 orh[4];
    #pragma unroll
    for (int q = 0; q < 4; q++)
        orh[q] = __floats2half2_rn(v[q * 2], v[q * 2 + 1]);
    ((float4*)g_rst16)[(size_t)n * 32 + tl] = *(float4*)orh;

    float s = 0.f, sq = 0.f;
    #pragma unroll
    for (int q = 0; q < 8; q++) { s += v[q]; sq += v[q] * v[q]; }
    #pragma unroll
    for (int o = 16; o > 0; o >>= 1) {
        s  += __shfl_xor_sync(0xffffffffu, s, o);
        sq += __shfl_xor_sync(0xffffffffu, sq, o);
    }
    float mu  = s * (1.0f / 256.0f);
    float var = sq * (1.0f / 256.0f) - mu * mu;
    float rs  = rsqrtf(var + 1e-5f);

    float4 g0 = *(const float4*)(ln2_g + tl * 8);
    float4 g1 = *(const float4*)(ln2_g + tl * 8 + 4);
    float4 b0 = *(const float4*)(ln2_b + tl * 8);
    float4 b1 = *(const float4*)(ln2_b + tl * 8 + 4);
    float y[8];
    y[0] = (v[0] - mu) * rs * g0.x + b0.x;
    y[1] = (v[1] - mu) * rs * g0.y + b0.y;
    y[2] = (v[2] - mu) * rs * g0.z + b0.z;
    y[3] = (v[3] - mu) * rs * g0.w + b0.w;
    y[4] = (v[4] - mu) * rs * g1.x + b1.x;
    y[5] = (v[5] - mu) * rs * g1.y + b1.y;
    y[6] = (v[6] - mu) * rs * g1.z + b1.z;
    y[7] = (v[7] - mu) * rs * g1.w + b1.w;
    __half2 oh[4];
    #pragma unroll
    for (int q = 0; q < 4; q++)
        oh[q] = __floats2half2_rn(y[q * 2], y[q * 2 + 1]);
    ((float4*)g_x16)[(size_t)n * 32 + tl] = *(float4*)oh;
}

// ---------------------------------------------------------------------------
extern "C" void kernel_launch(void* const* d_in, const int* in_sizes, int n_in,
                              void* d_out, int out_size) {
    const float* ent_feat = (const float*)d_in[0];
    const float* W_ent    = (const float*)d_in[1];
    const float* attn_h   = (const float*)d_in[2];
    const float* attn_t   = (const float*)d_in[3];
    const float* ln1_g    = (const float*)d_in[4];
    const float* ln1_b    = (const float*)d_in[5];
    const float* ln2_g    = (const float*)d_in[6];
    const float* ln2_b    = (const float*)d_in[7];
    const float* W1       = (const float*)d_in[8];
    const float* b1       = (const float*)d_in[9];
    const float* W2       = (const float*)d_in[10];
    const float* b2       = (const float*)d_in[11];
    const int*   src      = (const int*)d_in[12];
    float*       out      = (float*)d_out;

    const int SMEM = 2 * 40960;   // 81920: 2-stage double buffer, BK=64
    cudaFuncSetAttribute(gemm_mma<0>, cudaFuncAttributeMaxDynamicSharedMemorySize, SMEM);
    cudaFuncSetAttribute(gemm_mma<1>, cudaFuncAttributeMaxDynamicSharedMemorySize, SMEM);
    cudaFuncSetAttribute(gemm_mma<2>, cudaFuncAttributeMaxDynamicSharedMemorySize, SMEM);

    __half *p_h16, *p_f016, *p_x16, *p_t16, *p_rst16;
    __half *p_went16, *p_w116, *p_w216;
    cudaGetSymbolAddress((void**)&p_h16,    g_h16);
    cudaGetSymbolAddress((void**)&p_f016,   g_f016);
    cudaGetSymbolAddress((void**)&p_x16,    g_x16);
    cudaGetSymbolAddress((void**)&p_t16,    g_t16);
    cudaGetSymbolAddress((void**)&p_rst16,  g_rst16);
    cudaGetSymbolAddress((void**)&p_went16, g_went16);
    cudaGetSymbolAddress((void**)&p_w116,   g_w116);
    cudaGetSymbolAddress((void**)&p_w216,   g_w216);

    // 1. fused LN1 + weight conversion
    prep_kernel<<<LN_BLOCKS + WC_BLOCKS, 256>>>(ent_feat, ln1_g, ln1_b, p_h16,
                                                W_ent, W1, W2);

    // 2. feat0 = h @ W_ent^T -> fp16, fused eh/et
    {
        dim3 grid(DOUT / 128, (NN + 127) / 128);
        gemm_mma<0><<<grid, 256, SMEM>>>(p_h16, p_went16, nullptr, nullptr,
                                         nullptr, p_f016, attn_h, attn_t,
                                         NN, DOUT, DIN);
    }

    // 3. fused softmax + hop0 (warp-autonomous)
    hop0v_kernel<<<NN / 8, 256>>>(src);

    // 4-6. hops 1..3 vectorized
    for (int hop = 1; hop < HOPS - 1; hop++)
        hop16v_kernel<<<NN / 8, 256>>>(src, hop);

    // 7. final hop + fp16 residual + warp-local LN2 (rst stored fp16)
    hoplastv_kernel<<<NN / 8, 256>>>(src, ln2_g, ln2_b);

    // 8. t = relu(x @ W1^T + b1) -> fp16
    {
        dim3 grid(DFF / 128, (NN + 127) / 128);
        gemm_mma<1><<<grid, 256, SMEM>>>(p_x16, p_w116, b1, nullptr,
                                         nullptr, p_t16, nullptr, nullptr,
                                         NN, DFF, DOUT);
    }

    // 9. out = t @ W2^T + b2 + rst16  (fp32 out)
    {
        dim3 grid(DOUT / 128, (NN + 127) / 128);
        gemm_mma<2><<<grid, 256, SMEM>>>(p_t16, p_w216, b2, p_rst16,
                                         out, nullptr, nullptr, nullptr,
                                         NN, DOUT, DFF);
    }
}